// round 15
// baseline (speedup 1.0000x reference)
#include <cuda_runtime.h>
#include <cuda_bf16.h>
#include <cuda_fp16.h>
#include <math.h>
#include <stdint.h>

#define BBATCH 4
#define LL    2048
#define HH    1024
#define NQH   8
#define NKVH  2
#define DD    256
#define II    3584
#define VV    16384
#define NTOK  (BBATCH*LL)
#define FMIN  (-3.402823466e38f)
#define NQKV  5120          // 4096 q+gate | 512 k | 512 v
#define NGU   7168          // interleaved: row 2j = gate_j, row 2j+1 = up_j

// fp32 scratch
__device__ __align__(256) float g_x0    [(size_t)NTOK * HH];
__device__ __align__(256) float g_qkv   [(size_t)NTOK * NQKV];
__device__ __align__(256) float g_scores[(size_t)BBATCH * NQH * LL * LL];
__device__ __align__(256) float g_x1    [(size_t)NTOK * HH];
__device__ __align__(256) float g_x2    [(size_t)NTOK * HH];
// fp16 GEMM activation inputs
__device__ __align__(256) __half a_xcat [(size_t)NTOK * 2048];
__device__ __align__(256) __half a_xn   [(size_t)NTOK * HH];
__device__ __align__(256) __half a_ao   [(size_t)NTOK * 2048];
__device__ __align__(256) __half a_xn2  [(size_t)NTOK * HH];
__device__ __align__(256) __half a_gml  [(size_t)NTOK * II];
__device__ __align__(256) __half a_xn3  [(size_t)NTOK * HH];
// fp16 weights
__device__ __align__(256) __half w_fc   [(size_t)HH * 2048];
__device__ __align__(256) __half w_qkv  [(size_t)NQKV * HH];
__device__ __align__(256) __half w_o    [(size_t)HH * 2048];
__device__ __align__(256) __half w_gu   [(size_t)NGU * HH];     // interleaved
__device__ __align__(256) __half w_down [(size_t)HH * II];
__device__ __align__(256) __half w_lm   [(size_t)VV * HH];
// bf16 attention buffers
__device__ __align__(256) __nv_bfloat16 h_q [(size_t)BBATCH * NQH * LL * DD];
__device__ __align__(256) __nv_bfloat16 h_k [(size_t)BBATCH * NKVH * LL * DD];
__device__ __align__(256) __nv_bfloat16 h_vt[(size_t)BBATCH * NKVH * DD * LL];
__device__ __align__(256) __nv_bfloat16 h_p [(size_t)BBATCH * NQH * LL * LL];

// ---------------- helpers ----------------
__device__ __forceinline__ uint32_t smem_u32(const void* p) {
    uint32_t a;
    asm("{ .reg .u64 t; cvta.to.shared.u64 t, %1; cvt.u32.u64 %0, t; }" : "=r"(a) : "l"(p));
    return a;
}
#define SWZ(o) ((o) ^ (((o) >> 3) & 0x70))

__device__ __forceinline__ void cp16(uint32_t dst, const void* src) {
    asm volatile("cp.async.cg.shared.global [%0], [%1], 16;" :: "r"(dst), "l"(src));
}
__device__ __forceinline__ void cp_commit() { asm volatile("cp.async.commit_group;"); }
template<int N> __device__ __forceinline__ void cp_wait() {
    asm volatile("cp.async.wait_group %0;" :: "n"(N));
}
__device__ __forceinline__ void ldm_x4(uint32_t* r, uint32_t addr) {
    asm volatile("ldmatrix.sync.aligned.m8n8.x4.shared.b16 {%0,%1,%2,%3}, [%4];"
                 : "=r"(r[0]), "=r"(r[1]), "=r"(r[2]), "=r"(r[3]) : "r"(addr));
}
__device__ __forceinline__ void mma_fp16(float* c, const uint32_t* a, const uint32_t* b) {
    asm volatile(
        "mma.sync.aligned.m16n8k16.row.col.f32.f16.f16.f32 "
        "{%0,%1,%2,%3},{%4,%5,%6,%7},{%8,%9},{%0,%1,%2,%3};"
        : "+f"(c[0]), "+f"(c[1]), "+f"(c[2]), "+f"(c[3])
        : "r"(a[0]), "r"(a[1]), "r"(a[2]), "r"(a[3]), "r"(b[0]), "r"(b[1]));
}
__device__ __forceinline__ void mma_bf16(float* c, const uint32_t* a, const uint32_t* b) {
    asm volatile(
        "mma.sync.aligned.m16n8k16.row.col.f32.bf16.bf16.f32 "
        "{%0,%1,%2,%3},{%4,%5,%6,%7},{%8,%9},{%0,%1,%2,%3};"
        : "+f"(c[0]), "+f"(c[1]), "+f"(c[2]), "+f"(c[3])
        : "r"(a[0]), "r"(a[1]), "r"(a[2]), "r"(a[3]), "r"(b[0]), "r"(b[1]));
}

// block reduce (256 thr)
__device__ __forceinline__ float blk_sum(float v) {
    __shared__ float sh[8]; __shared__ float res;
    #pragma unroll
    for (int o = 16; o; o >>= 1) v += __shfl_xor_sync(0xffffffffu, v, o);
    if ((threadIdx.x & 31) == 0) sh[threadIdx.x >> 5] = v;
    __syncthreads();
    if (threadIdx.x < 32) {
        float x = (threadIdx.x < 8) ? sh[threadIdx.x] : 0.f;
        #pragma unroll
        for (int o = 4; o; o >>= 1) x += __shfl_xor_sync(0xffffffffu, x, o);
        if (threadIdx.x == 0) res = x;
    }
    __syncthreads();
    return res;
}
__device__ __forceinline__ float blk_max(float v) {
    __shared__ float sh[8]; __shared__ float res;
    #pragma unroll
    for (int o = 16; o; o >>= 1) v = fmaxf(v, __shfl_xor_sync(0xffffffffu, v, o));
    if ((threadIdx.x & 31) == 0) sh[threadIdx.x >> 5] = v;
    __syncthreads();
    if (threadIdx.x < 32) {
        float x = (threadIdx.x < 8) ? sh[threadIdx.x] : -INFINITY;
        #pragma unroll
        for (int o = 4; o; o >>= 1) x = fmaxf(x, __shfl_xor_sync(0xffffffffu, x, o));
        if (threadIdx.x == 0) res = x;
    }
    __syncthreads();
    return res;
}

// ---------------- fp16 mma GEMM: C[M,N] f32 = A[M,K]*B[N,K]^T ----------------
// CTA 128x256, warp 64x64. STAGES=4 safe: K>=1024 -> ntiles>=16.
// epi 0: plain  1: +R  4: interleaved silu -> fp16 CH [M, N/2]
#define FSTAGES 4
#define FSTAGE_BYTES (16384 + 32768)
#define FGEMM_SMEM (FSTAGES * FSTAGE_BYTES)

__global__ __launch_bounds__(256)
void gemm_fp16_kernel(const __half* __restrict__ A, const __half* __restrict__ B,
                      float* __restrict__ C, const float* __restrict__ R,
                      __half* __restrict__ CH,
                      int M, int N, int K, int epi)
{
    extern __shared__ char smch[];
    int tid = threadIdx.x;
    int m0 = blockIdx.y * 128;
    int n0 = blockIdx.x * 256;

    uint32_t smu = smem_u32(smch);
    int ntiles = K / 64;

    int lr = tid >> 3;
    int lc = (tid & 7) * 16;

    auto issue = [&](int t, int slot) {
        uint32_t bA = smu + slot * FSTAGE_BYTES;
        uint32_t bB = bA + 16384;
        long long kofs = (long long)t * 128;
        #pragma unroll
        for (int j = 0; j < 4; ++j) {
            int r = lr + j * 32;
            cp16(bA + SWZ(r * 128 + lc),
                 (const char*)(A + (long long)(m0 + r) * K) + kofs + lc);
        }
        #pragma unroll
        for (int j = 0; j < 8; ++j) {
            int r = lr + j * 32;
            cp16(bB + SWZ(r * 128 + lc),
                 (const char*)(B + (long long)(n0 + r) * K) + kofs + lc);
        }
        cp_commit();
    };

    int wid = tid >> 5, lane = tid & 31;
    int warp_m = (wid & 1) * 64;
    int warp_n = (wid >> 1) * 64;
    int blk = lane >> 3;
    int arow = (blk & 1) * 8 + (lane & 7);
    int achk = (blk >> 1) * 16;
    int brow = (blk >> 1) * 8 + (lane & 7);
    int bchk = (blk & 1) * 16;

    float acc[4][8][4];
    #pragma unroll
    for (int i = 0; i < 4; i++)
        #pragma unroll
        for (int j = 0; j < 8; j++)
            #pragma unroll
            for (int q = 0; q < 4; q++) acc[i][j][q] = 0.f;

    for (int s = 0; s < FSTAGES - 1; ++s) issue(s, s);

    for (int t = 0; t < ntiles; ++t) {
        cp_wait<FSTAGES - 2>();
        __syncthreads();
        if (t + FSTAGES - 1 < ntiles) issue(t + FSTAGES - 1, (t + FSTAGES - 1) % FSTAGES);
        uint32_t bA = smu + (t % FSTAGES) * FSTAGE_BYTES;
        uint32_t bB = bA + 16384;
        #pragma unroll
        for (int kk = 0; kk < 4; ++kk) {
            uint32_t af[4][4], bf[8][2];
            #pragma unroll
            for (int mi = 0; mi < 4; ++mi) {
                int row = warp_m + mi * 16 + arow;
                ldm_x4(af[mi], bA + SWZ(row * 128 + kk * 32 + achk));
            }
            #pragma unroll
            for (int nh = 0; nh < 4; ++nh) {
                uint32_t q[4];
                int n = warp_n + nh * 16 + brow;
                ldm_x4(q, bB + SWZ(n * 128 + kk * 32 + bchk));
                bf[nh * 2 + 0][0] = q[0]; bf[nh * 2 + 0][1] = q[1];
                bf[nh * 2 + 1][0] = q[2]; bf[nh * 2 + 1][1] = q[3];
            }
            #pragma unroll
            for (int mi = 0; mi < 4; ++mi)
                #pragma unroll
                for (int ni = 0; ni < 8; ++ni)
                    mma_fp16(acc[mi][ni], af[mi], bf[ni]);
        }
    }

    int g = lane >> 2, t4 = lane & 3;
    #pragma unroll
    for (int mi = 0; mi < 4; ++mi) {
        int r0 = m0 + warp_m + mi * 16 + g;
        int r1 = r0 + 8;
        #pragma unroll
        for (int ni = 0; ni < 8; ++ni) {
            int col = n0 + warp_n + ni * 8 + t4 * 2;
            float v0 = acc[mi][ni][0], v1 = acc[mi][ni][1];
            float v2 = acc[mi][ni][2], v3 = acc[mi][ni][3];
            if (epi == 4) {
                int oc = col >> 1;
                int halfN = N >> 1;
                float s0 = v0 * (1.f / (1.f + expf(-v0))) * v1;
                float s1 = v2 * (1.f / (1.f + expf(-v2))) * v3;
                CH[(long long)r0 * halfN + oc] = __float2half(s0);
                CH[(long long)r1 * halfN + oc] = __float2half(s1);
            } else {
                if (epi == 1) {
                    long long o0 = (long long)r0 * N + col;
                    long long o1 = (long long)r1 * N + col;
                    v0 += R[o0]; v1 += R[o0 + 1]; v2 += R[o1]; v3 += R[o1 + 1];
                }
                *(float2*)&C[(long long)r0 * N + col] = make_float2(v0, v1);
                *(float2*)&C[(long long)r1 * N + col] = make_float2(v2, v3);
            }
        }
    }
}

// ---------------- bf16 mma GEMM (attention): CTA 128x256, warp 64x64 ----------------
// STAGES=3 (klimit path has ntiles as low as 2; wait<1> forces group-0 done).
// epi 2: scores (scale+causal, skip masked 256-blocks)   3: PV + sigmoid-gate -> fp16 ao
#define BSTAGES 3
#define BSTAGE_BYTES (16384 + 32768)
#define BGEMM_SMEM (BSTAGES * BSTAGE_BYTES)

__global__ __launch_bounds__(256)
void gemm_bf16_kernel(const __nv_bfloat16* __restrict__ A, const __nv_bfloat16* __restrict__ B,
                      float* __restrict__ C,
                      const float* __restrict__ QKV, __half* __restrict__ AO,
                      int M, int N, int K,
                      long long bAel, long long bBel, long long bCel,
                      int bmode, int epi, float scale, int klimit)
{
    extern __shared__ char smch[];
    int tid = threadIdx.x;
    int z = blockIdx.z;
    int m0 = blockIdx.y * 128;
    int n0 = blockIdx.x * 256;
    if (epi == 2 && n0 > m0 + 127) return;

    const __nv_bfloat16* Ab = A + (long long)z * bAel;
    long long zb = bmode ? ((long long)(z >> 3) * 2 + ((z & 7) >> 2)) : (long long)z;
    const __nv_bfloat16* Bb = B + zb * bBel;
    float* Cb = C + (long long)z * bCel;

    uint32_t smu = smem_u32(smch);
    int Keff = klimit ? min(K, m0 + 128) : K;
    int ntiles = Keff / 64;

    int lr = tid >> 3;
    int lc = (tid & 7) * 16;

    auto issue = [&](int t, int slot) {
        uint32_t bA = smu + slot * BSTAGE_BYTES;
        uint32_t bB = bA + 16384;
        long long kofs = (long long)t * 128;
        #pragma unroll
        for (int j = 0; j < 4; ++j) {
            int r = lr + j * 32;
            cp16(bA + SWZ(r * 128 + lc),
                 (const char*)(Ab + (long long)(m0 + r) * K) + kofs + lc);
        }
        #pragma unroll
        for (int j = 0; j < 8; ++j) {
            int r = lr + j * 32;
            cp16(bB + SWZ(r * 128 + lc),
                 (const char*)(Bb + (long long)(n0 + r) * K) + kofs + lc);
        }
        cp_commit();
    };

    int wid = tid >> 5, lane = tid & 31;
    int warp_m = (wid & 1) * 64;
    int warp_n = (wid >> 1) * 64;
    int blk = lane >> 3;
    int arow = (blk & 1) * 8 + (lane & 7);
    int achk = (blk >> 1) * 16;
    int brow = (blk >> 1) * 8 + (lane & 7);
    int bchk = (blk & 1) * 16;

    float acc[4][8][4];
    #pragma unroll
    for (int i = 0; i < 4; i++)
        #pragma unroll
        for (int j = 0; j < 8; j++)
            #pragma unroll
            for (int q = 0; q < 4; q++) acc[i][j][q] = 0.f;

    int pre = ntiles < (BSTAGES - 1) ? ntiles : (BSTAGES - 1);
    for (int s = 0; s < pre; ++s) issue(s, s);

    for (int t = 0; t < ntiles; ++t) {
        cp_wait<BSTAGES - 2>();
        __syncthreads();
        if (t + BSTAGES - 1 < ntiles) issue(t + BSTAGES - 1, (t + BSTAGES - 1) % BSTAGES);
        uint32_t bA = smu + (t % BSTAGES) * BSTAGE_BYTES;
        uint32_t bB = bA + 16384;
        #pragma unroll
        for (int kk = 0; kk < 4; ++kk) {
            uint32_t af[4][4], bf[8][2];
            #pragma unroll
            for (int mi = 0; mi < 4; ++mi) {
                int row = warp_m + mi * 16 + arow;
                ldm_x4(af[mi], bA + SWZ(row * 128 + kk * 32 + achk));
            }
            #pragma unroll
            for (int nh = 0; nh < 4; ++nh) {
                uint32_t q[4];
                int n = warp_n + nh * 16 + brow;
                ldm_x4(q, bB + SWZ(n * 128 + kk * 32 + bchk));
                bf[nh * 2 + 0][0] = q[0]; bf[nh * 2 + 0][1] = q[1];
                bf[nh * 2 + 1][0] = q[2]; bf[nh * 2 + 1][1] = q[3];
            }
            #pragma unroll
            for (int mi = 0; mi < 4; ++mi)
                #pragma unroll
                for (int ni = 0; ni < 8; ++ni)
                    mma_bf16(acc[mi][ni], af[mi], bf[ni]);
        }
    }

    int g = lane >> 2, t4 = lane & 3;
    int bb = z >> 3, hh = z & 7;
    #pragma unroll
    for (int mi = 0; mi < 4; ++mi) {
        int r0 = m0 + warp_m + mi * 16 + g;
        int r1 = r0 + 8;
        #pragma unroll
        for (int ni = 0; ni < 8; ++ni) {
            int col = n0 + warp_n + ni * 8 + t4 * 2;
            float v0 = acc[mi][ni][0], v1 = acc[mi][ni][1];
            float v2 = acc[mi][ni][2], v3 = acc[mi][ni][3];
            if (epi == 2) {
                v0 *= scale; v1 *= scale; v2 *= scale; v3 *= scale;
                if (col     > r0) v0 = FMIN;
                if (col + 1 > r0) v1 = FMIN;
                if (col     > r1) v2 = FMIN;
                if (col + 1 > r1) v3 = FMIN;
                *(float2*)&Cb[(long long)r0 * N + col] = make_float2(v0, v1);
                *(float2*)&Cb[(long long)r1 * N + col] = make_float2(v2, v3);
            } else {   // epi 3, N=DD=256 so n0=0
                long long t0 = (long long)bb * LL + r0;
                long long t1 = (long long)bb * LL + r1;
                float g0 = QKV[t0 * NQKV + hh * 512 + 256 + col];
                float g1 = QKV[t0 * NQKV + hh * 512 + 256 + col + 1];
                float g2 = QKV[t1 * NQKV + hh * 512 + 256 + col];
                float g3 = QKV[t1 * NQKV + hh * 512 + 256 + col + 1];
                __half2 o0 = __floats2half2_rn(v0 * (1.f / (1.f + expf(-g0))),
                                               v1 * (1.f / (1.f + expf(-g1))));
                __half2 o1 = __floats2half2_rn(v2 * (1.f / (1.f + expf(-g2))),
                                               v3 * (1.f / (1.f + expf(-g3))));
                *(__half2*)&AO[t0 * 2048 + hh * 256 + col] = o0;
                *(__half2*)&AO[t1 * 2048 + hh * 256 + col] = o1;
            }
        }
    }
}

// ---------------- elementwise kernels ----------------
__global__ void convert_fp16_kernel(const float* __restrict__ in, __half* __restrict__ out, long n4) {
    long i = (long)blockIdx.x * 256 + threadIdx.x;
    if (i < n4) {
        float4 v = ((const float4*)in)[i];
        ((__half2*)out)[i * 2]     = __floats2half2_rn(v.x, v.y);
        ((__half2*)out)[i * 2 + 1] = __floats2half2_rn(v.z, v.w);
    }
}
__global__ void convert_ileave_kernel(const float* __restrict__ in, __half* __restrict__ out,
                                      long n4, int phase) {
    long i = (long)blockIdx.x * 256 + threadIdx.x;
    if (i < n4) {
        float4 v = ((const float4*)in)[i];
        long e = i * 4;
        long row = e >> 10;
        long col = e & 1023;
        __half* dst = out + ((row * 2 + phase) << 10) + col;
        ((__half2*)dst)[0] = __floats2half2_rn(v.x, v.y);
        ((__half2*)dst)[1] = __floats2half2_rn(v.z, v.w);
    }
}
__global__ void rmsnorm_h_kernel(const float* __restrict__ in, const float* __restrict__ w,
                                 __half* __restrict__ out, int width,
                                 long row_stride, long col_off) {
    long t = blockIdx.x;
    const float* x = in + t * width;
    float ss = 0.f;
    for (int i = threadIdx.x; i < width; i += 256) { float v = x[i]; ss = fmaf(v, v, ss); }
    float rms = rsqrtf(blk_sum(ss) / (float)width + 1e-6f);
    __half* y = out + t * row_stride + col_off;
    for (int i = threadIdx.x; i < width; i += 256) y[i] = __float2half(x[i] * rms * w[i]);
}
__global__ void qpost_kernel(const float* __restrict__ qkv, const float* __restrict__ qn_w,
                             __nv_bfloat16* __restrict__ qdst) {
    int t = blockIdx.x, h = blockIdx.y;
    int b = t / LL, l = t % LL;
    const float* src = qkv + (long)t * NQKV + h * 512;
    int tid = threadIdx.x;
    float v = src[tid];
    float rms = rsqrtf(blk_sum(v * v) / (float)DD + 1e-6f);
    __shared__ float sq[DD];
    sq[tid] = v * rms * qn_w[tid];
    __syncthreads();
    if (tid < 32) {
        float inv = powf(10000000.f, -2.f * (float)tid / 64.f);
        float fr = (float)l * inv;
        float c = cosf(fr), s = sinf(fr);
        float x0 = sq[2 * tid], x1 = sq[2 * tid + 1];
        sq[2 * tid]     = x0 * c - x1 * s;
        sq[2 * tid + 1] = x0 * s + x1 * c;
    }
    __syncthreads();
    long row = (long)(b * NQH + h) * LL + l;
    qdst[row * DD + tid] = __float2bfloat16(sq[tid]);
}
__global__ void kpost_kernel(const float* __restrict__ qkv, const float* __restrict__ kn_w,
                             __nv_bfloat16* __restrict__ kdst) {
    int t = blockIdx.x, h = blockIdx.y;
    int b = t / LL, l = t % LL;
    const float* src = qkv + (long)t * NQKV + 4096 + h * 256;
    int tid = threadIdx.x;
    float v = src[tid];
    float rms = rsqrtf(blk_sum(v * v) / (float)DD + 1e-6f);
    __shared__ float sq[DD];
    sq[tid] = v * rms * kn_w[tid];
    __syncthreads();
    if (tid < 32) {
        float inv = powf(10000000.f, -2.f * (float)tid / 64.f);
        float fr = (float)l * inv;
        float c = cosf(fr), s = sinf(fr);
        float x0 = sq[2 * tid], x1 = sq[2 * tid + 1];
        sq[2 * tid]     = x0 * c - x1 * s;
        sq[2 * tid + 1] = x0 * s + x1 * c;
    }
    __syncthreads();
    long row = (long)(b * NKVH + h) * LL + l;
    kdst[row * DD + tid] = __float2bfloat16(sq[tid]);
}
__global__ void vpost_kernel(const float* __restrict__ qkv, __nv_bfloat16* __restrict__ vt) {
    __shared__ float smv[32][33];
    int l0 = blockIdx.x * 32, d0 = blockIdx.y * 32, z = blockIdx.z;
    int b = z >> 1, h = z & 1;
    int tx = threadIdx.x & 31, ty = threadIdx.x >> 5;
    #pragma unroll
    for (int j = 0; j < 4; ++j) {
        int lloc = ty + j * 8;
        smv[lloc][tx] = qkv[(long)(b * LL + l0 + lloc) * NQKV + 4608 + h * 256 + d0 + tx];
    }
    __syncthreads();
    #pragma unroll
    for (int j = 0; j < 4; ++j) {
        int dd = ty + j * 8;
        vt[(long)(z * DD + d0 + dd) * LL + l0 + tx] = __float2bfloat16(smv[tx][dd]);
    }
}
// softmax over 256-aligned written prefix
__global__ void softmax_kernel(const float* __restrict__ scores, __nv_bfloat16* __restrict__ p) {
    int q = blockIdx.x, z = blockIdx.y;
    const float* row = scores + ((long)z * LL + q) * LL;
    __nv_bfloat16* prow = p + ((long)z * LL + q) * LL;
    int nwrite = ((q >> 8) + 1) << 8;
    float vals[8], mx = -INFINITY;
    #pragma unroll
    for (int i = 0; i < 8; i++) {
        int col = threadIdx.x + i * 256;
        vals[i] = (col < nwrite) ? row[col] : -INFINITY;
        mx = fmaxf(mx, vals[i]);
    }
    mx = blk_max(mx);
    float sum = 0.f;
    #pragma unroll
    for (int i = 0; i < 8; i++) { vals[i] = __expf(vals[i] - mx); sum += vals[i]; }
    sum = blk_sum(sum);
    float invs = 1.f / sum;
    #pragma unroll
    for (int i = 0; i < 8; i++) {
        int col = threadIdx.x + i * 256;
        if (col < nwrite) prow[col] = __float2bfloat16(vals[i] * invs);
    }
}

// ---------------- launch ----------------
static void launch_fp16_s(cudaStream_t st, const __half* A, const __half* B, float* C,
                          const float* R, __half* CH, int M, int N, int K, int epi) {
    dim3 grid(N / 256, M / 128, 1);
    gemm_fp16_kernel<<<grid, 256, FGEMM_SMEM, st>>>(A, B, C, R, CH, M, N, K, epi);
}

extern "C" void kernel_launch(void* const* d_in, const int* in_sizes, int n_in,
                              void* d_out, int out_size) {
    (void)in_sizes; (void)n_in; (void)out_size;
    const float* embeddings = (const float*)d_in[0];
    const float* hidden     = (const float*)d_in[1];
    const float* pre_emb_w  = (const float*)d_in[2];
    const float* pre_hid_w  = (const float*)d_in[3];
    const float* fc_w       = (const float*)d_in[4];
    const float* in_ln_w    = (const float*)d_in[5];
    const float* q_w        = (const float*)d_in[6];
    const float* k_w        = (const float*)d_in[7];
    const float* v_w        = (const float*)d_in[8];
    const float* o_w        = (const float*)d_in[9];
    const float* qn_w       = (const float*)d_in[10];
    const float* kn_w       = (const float*)d_in[11];
    const float* post_ln_w  = (const float*)d_in[12];
    const float* gate_w     = (const float*)d_in[13];
    const float* up_w       = (const float*)d_in[14];
    const float* down_w     = (const float*)d_in[15];
    const float* norm_w     = (const float*)d_in[16];
    const float* lm_w       = (const float*)d_in[17];
    float* out = (float*)d_out;

    static bool inited = false;
    static float *p_x0, *p_qkv, *p_scores, *p_x1, *p_x2;
    static __half *pa_xcat, *pa_xn, *pa_ao, *pa_xn2, *pa_gml, *pa_xn3;
    static __half *pw_fc, *pw_qkv, *pw_o, *pw_gu, *pw_down, *pw_lm;
    static __nv_bfloat16 *ph_q, *ph_k, *ph_vt, *ph_p;
    static cudaStream_t s2;
    static cudaEvent_t evFork, evJoin;
    if (!inited) {
        cudaGetSymbolAddress((void**)&p_x0, g_x0);      cudaGetSymbolAddress((void**)&p_qkv, g_qkv);
        cudaGetSymbolAddress((void**)&p_scores, g_scores);
        cudaGetSymbolAddress((void**)&p_x1, g_x1);      cudaGetSymbolAddress((void**)&p_x2, g_x2);
        cudaGetSymbolAddress((void**)&pa_xcat, a_xcat); cudaGetSymbolAddress((void**)&pa_xn, a_xn);
        cudaGetSymbolAddress((void**)&pa_ao, a_ao);     cudaGetSymbolAddress((void**)&pa_xn2, a_xn2);
        cudaGetSymbolAddress((void**)&pa_gml, a_gml);   cudaGetSymbolAddress((void**)&pa_xn3, a_xn3);
        cudaGetSymbolAddress((void**)&pw_fc, w_fc);     cudaGetSymbolAddress((void**)&pw_qkv, w_qkv);
        cudaGetSymbolAddress((void**)&pw_o, w_o);       cudaGetSymbolAddress((void**)&pw_gu, w_gu);
        cudaGetSymbolAddress((void**)&pw_down, w_down); cudaGetSymbolAddress((void**)&pw_lm, w_lm);
        cudaGetSymbolAddress((void**)&ph_q, h_q);       cudaGetSymbolAddress((void**)&ph_k, h_k);
        cudaGetSymbolAddress((void**)&ph_vt, h_vt);     cudaGetSymbolAddress((void**)&ph_p, h_p);
        cudaFuncSetAttribute(gemm_fp16_kernel, cudaFuncAttributeMaxDynamicSharedMemorySize, FGEMM_SMEM);
        cudaFuncSetAttribute(gemm_bf16_kernel, cudaFuncAttributeMaxDynamicSharedMemorySize, BGEMM_SMEM);
        cudaStreamCreateWithFlags(&s2, cudaStreamNonBlocking);
        cudaEventCreateWithFlags(&evFork, cudaEventDisableTiming);
        cudaEventCreateWithFlags(&evJoin, cudaEventDisableTiming);
        inited = true;
    }

    long n4;
    n4 = (long)HH * 2048 / 4;  convert_fp16_kernel<<<(n4 + 255) / 256, 256>>>(fc_w, pw_fc, n4);
    n4 = (long)4096 * HH / 4;  convert_fp16_kernel<<<(n4 + 255) / 256, 256>>>(q_w, pw_qkv, n4);
    n4 = (long)512 * HH / 4;   convert_fp16_kernel<<<(n4 + 255) / 256, 256>>>(k_w, pw_qkv + (size_t)4096 * HH, n4);
    n4 = (long)512 * HH / 4;   convert_fp16_kernel<<<(n4 + 255) / 256, 256>>>(v_w, pw_qkv + (size_t)4608 * HH, n4);

    cudaEventRecord(evFork, 0);
    cudaStreamWaitEvent(s2, evFork, 0);
    n4 = (long)HH * 2048 / 4;  convert_fp16_kernel<<<(n4 + 255) / 256, 256, 0, s2>>>(o_w, pw_o, n4);
    n4 = (long)II * HH / 4;    convert_ileave_kernel<<<(n4 + 255) / 256, 256, 0, s2>>>(gate_w, pw_gu, n4, 0);
    n4 = (long)II * HH / 4;    convert_ileave_kernel<<<(n4 + 255) / 256, 256, 0, s2>>>(up_w,   pw_gu, n4, 1);
    n4 = (long)HH * II / 4;    convert_fp16_kernel<<<(n4 + 255) / 256, 256, 0, s2>>>(down_w, pw_down, n4);
    n4 = (long)VV * HH / 4;    convert_fp16_kernel<<<(n4 + 255) / 256, 256, 0, s2>>>(lm_w, pw_lm, n4);
    cudaEventRecord(evJoin, s2);

    rmsnorm_h_kernel<<<NTOK, 256>>>(embeddings, pre_emb_w, pa_xcat, HH, 2048, 0);
    rmsnorm_h_kernel<<<NTOK, 256>>>(hidden,     pre_hid_w, pa_xcat, HH, 2048, 1024);
    launch_fp16_s(0, pa_xcat, pw_fc, p_x0, nullptr, nullptr, NTOK, HH, 2048, 0);
    rmsnorm_h_kernel<<<NTOK, 256>>>(p_x0, in_ln_w, pa_xn, HH, 1024, 0);
    launch_fp16_s(0, pa_xn, pw_qkv, p_qkv, nullptr, nullptr, NTOK, NQKV, HH, 0);
    qpost_kernel<<<dim3(NTOK, NQH), 256>>>(p_qkv, qn_w, ph_q);
    kpost_kernel<<<dim3(NTOK, NKVH), 256>>>(p_qkv, kn_w, ph_k);
    vpost_kernel<<<dim3(LL / 32, DD / 32, BBATCH * NKVH), 256>>>(p_qkv, ph_vt);
    // scores = QK^T/16 causal (CTA 128x256, skip masked 256-blocks)
    {
        dim3 grid(LL / 256, LL / 128, BBATCH * NQH);
        gemm_bf16_kernel<<<grid, 256, BGEMM_SMEM>>>(ph_q, ph_k, p_scores, nullptr, nullptr,
            LL, LL, DD, (long long)LL * DD, (long long)LL * DD, (long long)LL * LL,
            1, 2, 0.0625f, 0);
    }
    softmax_kernel<<<dim3(LL, BBATCH * NQH), 256>>>(p_scores, ph_p);
    // PV + fused sigmoid gate -> fp16 ao (N = DD = 256 in one tile)
    {
        dim3 grid(DD / 256, LL / 128, BBATCH * NQH);
        gemm_bf16_kernel<<<grid, 256, BGEMM_SMEM>>>(ph_p, ph_vt, nullptr, p_qkv, pa_ao,
            LL, DD, LL, (long long)LL * LL, (long long)DD * LL, 0,
            1, 3, 1.f, 1);
    }
    cudaStreamWaitEvent(0, evJoin, 0);
    launch_fp16_s(0, pa_ao, pw_o, p_x1, p_x0, nullptr, NTOK, HH, 2048, 1);
    rmsnorm_h_kernel<<<NTOK, 256>>>(p_x1, post_ln_w, pa_xn2, HH, 1024, 0);
    launch_fp16_s(0, pa_xn2, pw_gu, nullptr, nullptr, pa_gml, NTOK, NGU, HH, 4);
    launch_fp16_s(0, pa_gml, pw_down, p_x2, p_x1, nullptr, NTOK, HH, II, 1);
    rmsnorm_h_kernel<<<NTOK, 256>>>(p_x2, norm_w, pa_xn3, HH, 1024, 0);
    launch_fp16_s(0, pa_xn3, pw_lm, out, nullptr, nullptr, NTOK, VV, HH, 0);
}

// round 16
// speedup vs baseline: 1.0481x; 1.0481x over previous
#include <cuda_runtime.h>
#include <cuda_bf16.h>
#include <cuda_fp16.h>
#include <math.h>
#include <stdint.h>

#define BBATCH 4
#define LL    2048
#define HH    1024
#define NQH   8
#define NKVH  2
#define DD    256
#define II    3584
#define VV    16384
#define NTOK  (BBATCH*LL)
#define FMIN  (-3.402823466e38f)
#define NQKV  5120          // 4096 q+gate | 512 k | 512 v
#define NGU   7168          // interleaved: row 2j = gate_j, row 2j+1 = up_j

// fp32 scratch
__device__ __align__(256) float g_x0    [(size_t)NTOK * HH];
__device__ __align__(256) float g_qkv   [(size_t)NTOK * NQKV];
__device__ __align__(256) float g_scores[(size_t)BBATCH * NQH * LL * LL];
__device__ __align__(256) float g_x1    [(size_t)NTOK * HH];
__device__ __align__(256) float g_x2    [(size_t)NTOK * HH];
// fp16 GEMM activation inputs
__device__ __align__(256) __half a_xcat [(size_t)NTOK * 2048];
__device__ __align__(256) __half a_xn   [(size_t)NTOK * HH];
__device__ __align__(256) __half a_ao   [(size_t)NTOK * 2048];
__device__ __align__(256) __half a_xn2  [(size_t)NTOK * HH];
__device__ __align__(256) __half a_gml  [(size_t)NTOK * II];
__device__ __align__(256) __half a_xn3  [(size_t)NTOK * HH];
// fp16 weights
__device__ __align__(256) __half w_fc   [(size_t)HH * 2048];
__device__ __align__(256) __half w_qkv  [(size_t)NQKV * HH];
__device__ __align__(256) __half w_o    [(size_t)HH * 2048];
__device__ __align__(256) __half w_gu   [(size_t)NGU * HH];     // interleaved
__device__ __align__(256) __half w_down [(size_t)HH * II];
__device__ __align__(256) __half w_lm   [(size_t)VV * HH];
// bf16 attention buffers
__device__ __align__(256) __nv_bfloat16 h_q [(size_t)BBATCH * NQH * LL * DD];
__device__ __align__(256) __nv_bfloat16 h_k [(size_t)BBATCH * NKVH * LL * DD];
__device__ __align__(256) __nv_bfloat16 h_vt[(size_t)BBATCH * NKVH * DD * LL];
__device__ __align__(256) __nv_bfloat16 h_p [(size_t)BBATCH * NQH * LL * LL];

// ---------------- helpers ----------------
__device__ __forceinline__ uint32_t smem_u32(const void* p) {
    uint32_t a;
    asm("{ .reg .u64 t; cvta.to.shared.u64 t, %1; cvt.u32.u64 %0, t; }" : "=r"(a) : "l"(p));
    return a;
}
#define SWZ(o) ((o) ^ (((o) >> 3) & 0x70))

__device__ __forceinline__ void cp16(uint32_t dst, const void* src) {
    asm volatile("cp.async.cg.shared.global [%0], [%1], 16;" :: "r"(dst), "l"(src));
}
__device__ __forceinline__ void cp_commit() { asm volatile("cp.async.commit_group;"); }
template<int N> __device__ __forceinline__ void cp_wait() {
    asm volatile("cp.async.wait_group %0;" :: "n"(N));
}
__device__ __forceinline__ void ldm_x4(uint32_t* r, uint32_t addr) {
    asm volatile("ldmatrix.sync.aligned.m8n8.x4.shared.b16 {%0,%1,%2,%3}, [%4];"
                 : "=r"(r[0]), "=r"(r[1]), "=r"(r[2]), "=r"(r[3]) : "r"(addr));
}
__device__ __forceinline__ void mma_fp16(float* c, const uint32_t* a, const uint32_t* b) {
    asm volatile(
        "mma.sync.aligned.m16n8k16.row.col.f32.f16.f16.f32 "
        "{%0,%1,%2,%3},{%4,%5,%6,%7},{%8,%9},{%0,%1,%2,%3};"
        : "+f"(c[0]), "+f"(c[1]), "+f"(c[2]), "+f"(c[3])
        : "r"(a[0]), "r"(a[1]), "r"(a[2]), "r"(a[3]), "r"(b[0]), "r"(b[1]));
}
__device__ __forceinline__ void mma_bf16(float* c, const uint32_t* a, const uint32_t* b) {
    asm volatile(
        "mma.sync.aligned.m16n8k16.row.col.f32.bf16.bf16.f32 "
        "{%0,%1,%2,%3},{%4,%5,%6,%7},{%8,%9},{%0,%1,%2,%3};"
        : "+f"(c[0]), "+f"(c[1]), "+f"(c[2]), "+f"(c[3])
        : "r"(a[0]), "r"(a[1]), "r"(a[2]), "r"(a[3]), "r"(b[0]), "r"(b[1]));
}

// block reduce (256 thr)
__device__ __forceinline__ float blk_sum(float v) {
    __shared__ float sh[8]; __shared__ float res;
    #pragma unroll
    for (int o = 16; o; o >>= 1) v += __shfl_xor_sync(0xffffffffu, v, o);
    if ((threadIdx.x & 31) == 0) sh[threadIdx.x >> 5] = v;
    __syncthreads();
    if (threadIdx.x < 32) {
        float x = (threadIdx.x < 8) ? sh[threadIdx.x] : 0.f;
        #pragma unroll
        for (int o = 4; o; o >>= 1) x += __shfl_xor_sync(0xffffffffu, x, o);
        if (threadIdx.x == 0) res = x;
    }
    __syncthreads();
    return res;
}
__device__ __forceinline__ float blk_max(float v) {
    __shared__ float sh[8]; __shared__ float res;
    #pragma unroll
    for (int o = 16; o; o >>= 1) v = fmaxf(v, __shfl_xor_sync(0xffffffffu, v, o));
    if ((threadIdx.x & 31) == 0) sh[threadIdx.x >> 5] = v;
    __syncthreads();
    if (threadIdx.x < 32) {
        float x = (threadIdx.x < 8) ? sh[threadIdx.x] : -INFINITY;
        #pragma unroll
        for (int o = 4; o; o >>= 1) x = fmaxf(x, __shfl_xor_sync(0xffffffffu, x, o));
        if (threadIdx.x == 0) res = x;
    }
    __syncthreads();
    return res;
}

// ---------------- fp16 mma GEMM: C[M,N] f32 = A[M,K]*B[N,K]^T ----------------
// CTA 128x256, warp 64x64. STAGES=4 safe: K>=1024 -> ntiles>=16.
// epi 0: plain  1: +R  4: interleaved silu -> fp16 CH [M, N/2]
#define FSTAGES 4
#define FSTAGE_BYTES (16384 + 32768)
#define FGEMM_SMEM (FSTAGES * FSTAGE_BYTES)

__global__ __launch_bounds__(256)
void gemm_fp16_kernel(const __half* __restrict__ A, const __half* __restrict__ B,
                      float* __restrict__ C, const float* __restrict__ R,
                      __half* __restrict__ CH,
                      int M, int N, int K, int epi)
{
    extern __shared__ char smch[];
    int tid = threadIdx.x;
    int m0 = blockIdx.y * 128;
    int n0 = blockIdx.x * 256;

    uint32_t smu = smem_u32(smch);
    int ntiles = K / 64;

    int lr = tid >> 3;
    int lc = (tid & 7) * 16;

    auto issue = [&](int t, int slot) {
        uint32_t bA = smu + slot * FSTAGE_BYTES;
        uint32_t bB = bA + 16384;
        long long kofs = (long long)t * 128;
        #pragma unroll
        for (int j = 0; j < 4; ++j) {
            int r = lr + j * 32;
            cp16(bA + SWZ(r * 128 + lc),
                 (const char*)(A + (long long)(m0 + r) * K) + kofs + lc);
        }
        #pragma unroll
        for (int j = 0; j < 8; ++j) {
            int r = lr + j * 32;
            cp16(bB + SWZ(r * 128 + lc),
                 (const char*)(B + (long long)(n0 + r) * K) + kofs + lc);
        }
        cp_commit();
    };

    int wid = tid >> 5, lane = tid & 31;
    int warp_m = (wid & 1) * 64;
    int warp_n = (wid >> 1) * 64;
    int blk = lane >> 3;
    int arow = (blk & 1) * 8 + (lane & 7);
    int achk = (blk >> 1) * 16;
    int brow = (blk >> 1) * 8 + (lane & 7);
    int bchk = (blk & 1) * 16;

    float acc[4][8][4];
    #pragma unroll
    for (int i = 0; i < 4; i++)
        #pragma unroll
        for (int j = 0; j < 8; j++)
            #pragma unroll
            for (int q = 0; q < 4; q++) acc[i][j][q] = 0.f;

    for (int s = 0; s < FSTAGES - 1; ++s) issue(s, s);

    for (int t = 0; t < ntiles; ++t) {
        cp_wait<FSTAGES - 2>();
        __syncthreads();
        if (t + FSTAGES - 1 < ntiles) issue(t + FSTAGES - 1, (t + FSTAGES - 1) % FSTAGES);
        uint32_t bA = smu + (t % FSTAGES) * FSTAGE_BYTES;
        uint32_t bB = bA + 16384;
        #pragma unroll
        for (int kk = 0; kk < 4; ++kk) {
            uint32_t af[4][4], bf[8][2];
            #pragma unroll
            for (int mi = 0; mi < 4; ++mi) {
                int row = warp_m + mi * 16 + arow;
                ldm_x4(af[mi], bA + SWZ(row * 128 + kk * 32 + achk));
            }
            #pragma unroll
            for (int nh = 0; nh < 4; ++nh) {
                uint32_t q[4];
                int n = warp_n + nh * 16 + brow;
                ldm_x4(q, bB + SWZ(n * 128 + kk * 32 + bchk));
                bf[nh * 2 + 0][0] = q[0]; bf[nh * 2 + 0][1] = q[1];
                bf[nh * 2 + 1][0] = q[2]; bf[nh * 2 + 1][1] = q[3];
            }
            #pragma unroll
            for (int mi = 0; mi < 4; ++mi)
                #pragma unroll
                for (int ni = 0; ni < 8; ++ni)
                    mma_fp16(acc[mi][ni], af[mi], bf[ni]);
        }
    }

    int g = lane >> 2, t4 = lane & 3;
    #pragma unroll
    for (int mi = 0; mi < 4; ++mi) {
        int r0 = m0 + warp_m + mi * 16 + g;
        int r1 = r0 + 8;
        #pragma unroll
        for (int ni = 0; ni < 8; ++ni) {
            int col = n0 + warp_n + ni * 8 + t4 * 2;
            float v0 = acc[mi][ni][0], v1 = acc[mi][ni][1];
            float v2 = acc[mi][ni][2], v3 = acc[mi][ni][3];
            if (epi == 4) {
                int oc = col >> 1;
                int halfN = N >> 1;
                float s0 = v0 * (1.f / (1.f + expf(-v0))) * v1;
                float s1 = v2 * (1.f / (1.f + expf(-v2))) * v3;
                CH[(long long)r0 * halfN + oc] = __float2half(s0);
                CH[(long long)r1 * halfN + oc] = __float2half(s1);
            } else {
                if (epi == 1) {
                    long long o0 = (long long)r0 * N + col;
                    long long o1 = (long long)r1 * N + col;
                    v0 += R[o0]; v1 += R[o0 + 1]; v2 += R[o1]; v3 += R[o1 + 1];
                }
                *(float2*)&C[(long long)r0 * N + col] = make_float2(v0, v1);
                *(float2*)&C[(long long)r1 * N + col] = make_float2(v2, v3);
            }
        }
    }
}

// ---------------- bf16 mma GEMM (attention): CTA 128x128, warp 64x32 (R14 proven) ----------------
// STAGES=3 (klimit path has ntiles as low as 2; wait<1> forces group-0 done).
// epi 2: scores (scale+causal, skip masked)   3: PV + sigmoid-gate -> fp16 ao
#define BSTAGES 3
#define BSTAGE_BYTES 32768
#define BGEMM_SMEM (BSTAGES * BSTAGE_BYTES)

__global__ __launch_bounds__(256)
void gemm_bf16_kernel(const __nv_bfloat16* __restrict__ A, const __nv_bfloat16* __restrict__ B,
                      float* __restrict__ C,
                      const float* __restrict__ QKV, __half* __restrict__ AO,
                      int M, int N, int K,
                      long long bAel, long long bBel, long long bCel,
                      int bmode, int epi, float scale, int klimit)
{
    extern __shared__ char smch[];
    int tid = threadIdx.x;
    int z = blockIdx.z;
    int m0 = blockIdx.y * 128;
    int n0 = blockIdx.x * 128;
    if (epi == 2 && n0 > m0 + 127) return;

    const __nv_bfloat16* Ab = A + (long long)z * bAel;
    long long zb = bmode ? ((long long)(z >> 3) * 2 + ((z & 7) >> 2)) : (long long)z;
    const __nv_bfloat16* Bb = B + zb * bBel;
    float* Cb = C + (long long)z * bCel;

    uint32_t smu = smem_u32(smch);
    int Keff = klimit ? min(K, m0 + 128) : K;
    int ntiles = Keff / 64;

    int lr = tid >> 3;
    int lc = (tid & 7) * 16;

    auto issue = [&](int t, int slot) {
        uint32_t bA = smu + slot * BSTAGE_BYTES;
        uint32_t bB = bA + 16384;
        long long kofs = (long long)t * 128;
        #pragma unroll
        for (int j = 0; j < 4; ++j) {
            int r = lr + j * 32;
            cp16(bA + SWZ(r * 128 + lc),
                 (const char*)(Ab + (long long)(m0 + r) * K) + kofs + lc);
        }
        #pragma unroll
        for (int j = 0; j < 4; ++j) {
            int r = lr + j * 32;
            cp16(bB + SWZ(r * 128 + lc),
                 (const char*)(Bb + (long long)(n0 + r) * K) + kofs + lc);
        }
        cp_commit();
    };

    int wid = tid >> 5, lane = tid & 31;
    int warp_m = (wid & 1) * 64;
    int warp_n = (wid >> 1) * 32;
    int blk = lane >> 3;
    int arow = (blk & 1) * 8 + (lane & 7);
    int achk = (blk >> 1) * 16;
    int brow = (blk >> 1) * 8 + (lane & 7);
    int bchk = (blk & 1) * 16;

    float acc[4][4][4];
    #pragma unroll
    for (int i = 0; i < 4; i++)
        #pragma unroll
        for (int j = 0; j < 4; j++)
            #pragma unroll
            for (int q = 0; q < 4; q++) acc[i][j][q] = 0.f;

    int pre = ntiles < (BSTAGES - 1) ? ntiles : (BSTAGES - 1);
    for (int s = 0; s < pre; ++s) issue(s, s);

    for (int t = 0; t < ntiles; ++t) {
        cp_wait<BSTAGES - 2>();
        __syncthreads();
        if (t + BSTAGES - 1 < ntiles) issue(t + BSTAGES - 1, (t + BSTAGES - 1) % BSTAGES);
        uint32_t bA = smu + (t % BSTAGES) * BSTAGE_BYTES;
        uint32_t bB = bA + 16384;
        #pragma unroll
        for (int kk = 0; kk < 4; ++kk) {
            uint32_t af[4][4], bf[4][2];
            #pragma unroll
            for (int mi = 0; mi < 4; ++mi) {
                int row = warp_m + mi * 16 + arow;
                ldm_x4(af[mi], bA + SWZ(row * 128 + kk * 32 + achk));
            }
            #pragma unroll
            for (int nh = 0; nh < 2; ++nh) {
                uint32_t q[4];
                int n = warp_n + nh * 16 + brow;
                ldm_x4(q, bB + SWZ(n * 128 + kk * 32 + bchk));
                bf[nh * 2 + 0][0] = q[0]; bf[nh * 2 + 0][1] = q[1];
                bf[nh * 2 + 1][0] = q[2]; bf[nh * 2 + 1][1] = q[3];
            }
            #pragma unroll
            for (int mi = 0; mi < 4; ++mi)
                #pragma unroll
                for (int ni = 0; ni < 4; ++ni)
                    mma_bf16(acc[mi][ni], af[mi], bf[ni]);
        }
    }

    int g = lane >> 2, t4 = lane & 3;
    int bb = z >> 3, hh = z & 7;
    #pragma unroll
    for (int mi = 0; mi < 4; ++mi) {
        int r0 = m0 + warp_m + mi * 16 + g;
        int r1 = r0 + 8;
        #pragma unroll
        for (int ni = 0; ni < 4; ++ni) {
            int col = n0 + warp_n + ni * 8 + t4 * 2;
            float v0 = acc[mi][ni][0], v1 = acc[mi][ni][1];
            float v2 = acc[mi][ni][2], v3 = acc[mi][ni][3];
            if (epi == 2) {
                v0 *= scale; v1 *= scale; v2 *= scale; v3 *= scale;
                if (col     > r0) v0 = FMIN;
                if (col + 1 > r0) v1 = FMIN;
                if (col     > r1) v2 = FMIN;
                if (col + 1 > r1) v3 = FMIN;
                *(float2*)&Cb[(long long)r0 * N + col] = make_float2(v0, v1);
                *(float2*)&Cb[(long long)r1 * N + col] = make_float2(v2, v3);
            } else {   // epi 3
                long long t0 = (long long)bb * LL + r0;
                long long t1 = (long long)bb * LL + r1;
                float g0 = QKV[t0 * NQKV + hh * 512 + 256 + col];
                float g1 = QKV[t0 * NQKV + hh * 512 + 256 + col + 1];
                float g2 = QKV[t1 * NQKV + hh * 512 + 256 + col];
                float g3 = QKV[t1 * NQKV + hh * 512 + 256 + col + 1];
                __half2 o0 = __floats2half2_rn(v0 * (1.f / (1.f + expf(-g0))),
                                               v1 * (1.f / (1.f + expf(-g1))));
                __half2 o1 = __floats2half2_rn(v2 * (1.f / (1.f + expf(-g2))),
                                               v3 * (1.f / (1.f + expf(-g3))));
                *(__half2*)&AO[t0 * 2048 + hh * 256 + col] = o0;
                *(__half2*)&AO[t1 * 2048 + hh * 256 + col] = o1;
            }
        }
    }
}

// ---------------- elementwise kernels ----------------
__global__ void convert_fp16_kernel(const float* __restrict__ in, __half* __restrict__ out, long n4) {
    long i = (long)blockIdx.x * 256 + threadIdx.x;
    if (i < n4) {
        float4 v = ((const float4*)in)[i];
        ((__half2*)out)[i * 2]     = __floats2half2_rn(v.x, v.y);
        ((__half2*)out)[i * 2 + 1] = __floats2half2_rn(v.z, v.w);
    }
}
__global__ void convert_ileave_kernel(const float* __restrict__ in, __half* __restrict__ out,
                                      long n4, int phase) {
    long i = (long)blockIdx.x * 256 + threadIdx.x;
    if (i < n4) {
        float4 v = ((const float4*)in)[i];
        long e = i * 4;
        long row = e >> 10;
        long col = e & 1023;
        __half* dst = out + ((row * 2 + phase) << 10) + col;
        ((__half2*)dst)[0] = __floats2half2_rn(v.x, v.y);
        ((__half2*)dst)[1] = __floats2half2_rn(v.z, v.w);
    }
}
// vectorized rmsnorm: width fixed 1024, 256 threads, one float4 per thread
__global__ void rmsnorm_h_kernel(const float* __restrict__ in, const float* __restrict__ w,
                                 __half* __restrict__ out,
                                 long row_stride, long col_off) {
    long t = blockIdx.x;
    int tid = threadIdx.x;
    float4 v = ((const float4*)(in + t * HH))[tid];
    float ss = v.x * v.x + v.y * v.y + v.z * v.z + v.w * v.w;
    float rms = rsqrtf(blk_sum(ss) / (float)HH + 1e-6f);
    float4 wv = ((const float4*)w)[tid];
    __half* y = out + t * row_stride + col_off + tid * 4;
    ((__half2*)y)[0] = __floats2half2_rn(v.x * rms * wv.x, v.y * rms * wv.y);
    ((__half2*)y)[1] = __floats2half2_rn(v.z * rms * wv.z, v.w * rms * wv.w);
}
__global__ void qpost_kernel(const float* __restrict__ qkv, const float* __restrict__ qn_w,
                             __nv_bfloat16* __restrict__ qdst) {
    int t = blockIdx.x, h = blockIdx.y;
    int b = t / LL, l = t % LL;
    const float* src = qkv + (long)t * NQKV + h * 512;
    int tid = threadIdx.x;
    float v = src[tid];
    float rms = rsqrtf(blk_sum(v * v) / (float)DD + 1e-6f);
    __shared__ float sq[DD];
    sq[tid] = v * rms * qn_w[tid];
    __syncthreads();
    if (tid < 32) {
        float inv = powf(10000000.f, -2.f * (float)tid / 64.f);
        float fr = (float)l * inv;
        float c = cosf(fr), s = sinf(fr);
        float x0 = sq[2 * tid], x1 = sq[2 * tid + 1];
        sq[2 * tid]     = x0 * c - x1 * s;
        sq[2 * tid + 1] = x0 * s + x1 * c;
    }
    __syncthreads();
    long row = (long)(b * NQH + h) * LL + l;
    qdst[row * DD + tid] = __float2bfloat16(sq[tid]);
}
__global__ void kpost_kernel(const float* __restrict__ qkv, const float* __restrict__ kn_w,
                             __nv_bfloat16* __restrict__ kdst) {
    int t = blockIdx.x, h = blockIdx.y;
    int b = t / LL, l = t % LL;
    const float* src = qkv + (long)t * NQKV + 4096 + h * 256;
    int tid = threadIdx.x;
    float v = src[tid];
    float rms = rsqrtf(blk_sum(v * v) / (float)DD + 1e-6f);
    __shared__ float sq[DD];
    sq[tid] = v * rms * kn_w[tid];
    __syncthreads();
    if (tid < 32) {
        float inv = powf(10000000.f, -2.f * (float)tid / 64.f);
        float fr = (float)l * inv;
        float c = cosf(fr), s = sinf(fr);
        float x0 = sq[2 * tid], x1 = sq[2 * tid + 1];
        sq[2 * tid]     = x0 * c - x1 * s;
        sq[2 * tid + 1] = x0 * s + x1 * c;
    }
    __syncthreads();
    long row = (long)(b * NKVH + h) * LL + l;
    kdst[row * DD + tid] = __float2bfloat16(sq[tid]);
}
__global__ void vpost_kernel(const float* __restrict__ qkv, __nv_bfloat16* __restrict__ vt) {
    __shared__ float smv[32][33];
    int l0 = blockIdx.x * 32, d0 = blockIdx.y * 32, z = blockIdx.z;
    int b = z >> 1, h = z & 1;
    int tx = threadIdx.x & 31, ty = threadIdx.x >> 5;
    #pragma unroll
    for (int j = 0; j < 4; ++j) {
        int lloc = ty + j * 8;
        smv[lloc][tx] = qkv[(long)(b * LL + l0 + lloc) * NQKV + 4608 + h * 256 + d0 + tx];
    }
    __syncthreads();
    #pragma unroll
    for (int j = 0; j < 4; ++j) {
        int dd = ty + j * 8;
        vt[(long)(z * DD + d0 + dd) * LL + l0 + tx] = __float2bfloat16(smv[tx][dd]);
    }
}
// softmax over 128-aligned written prefix (R14 config)
__global__ void softmax_kernel(const float* __restrict__ scores, __nv_bfloat16* __restrict__ p) {
    int q = blockIdx.x, z = blockIdx.y;
    const float* row = scores + ((long)z * LL + q) * LL;
    __nv_bfloat16* prow = p + ((long)z * LL + q) * LL;
    int nwrite = ((q >> 7) + 1) << 7;
    float vals[8], mx = -INFINITY;
    #pragma unroll
    for (int i = 0; i < 8; i++) {
        int col = threadIdx.x + i * 256;
        vals[i] = (col < nwrite) ? row[col] : -INFINITY;
        mx = fmaxf(mx, vals[i]);
    }
    mx = blk_max(mx);
    float sum = 0.f;
    #pragma unroll
    for (int i = 0; i < 8; i++) { vals[i] = __expf(vals[i] - mx); sum += vals[i]; }
    sum = blk_sum(sum);
    float invs = 1.f / sum;
    #pragma unroll
    for (int i = 0; i < 8; i++) {
        int col = threadIdx.x + i * 256;
        if (col < nwrite) prow[col] = __float2bfloat16(vals[i] * invs);
    }
}

// ---------------- launch ----------------
static void launch_fp16_s(cudaStream_t st, const __half* A, const __half* B, float* C,
                          const float* R, __half* CH, int M, int N, int K, int epi) {
    dim3 grid(N / 256, M / 128, 1);
    gemm_fp16_kernel<<<grid, 256, FGEMM_SMEM, st>>>(A, B, C, R, CH, M, N, K, epi);
}

extern "C" void kernel_launch(void* const* d_in, const int* in_sizes, int n_in,
                              void* d_out, int out_size) {
    (void)in_sizes; (void)n_in; (void)out_size;
    const float* embeddings = (const float*)d_in[0];
    const float* hidden     = (const float*)d_in[1];
    const float* pre_emb_w  = (const float*)d_in[2];
    const float* pre_hid_w  = (const float*)d_in[3];
    const float* fc_w       = (const float*)d_in[4];
    const float* in_ln_w    = (const float*)d_in[5];
    const float* q_w        = (const float*)d_in[6];
    const float* k_w        = (const float*)d_in[7];
    const float* v_w        = (const float*)d_in[8];
    const float* o_w        = (const float*)d_in[9];
    const float* qn_w       = (const float*)d_in[10];
    const float* kn_w       = (const float*)d_in[11];
    const float* post_ln_w  = (const float*)d_in[12];
    const float* gate_w     = (const float*)d_in[13];
    const float* up_w       = (const float*)d_in[14];
    const float* down_w     = (const float*)d_in[15];
    const float* norm_w     = (const float*)d_in[16];
    const float* lm_w       = (const float*)d_in[17];
    float* out = (float*)d_out;

    static bool inited = false;
    static float *p_x0, *p_qkv, *p_scores, *p_x1, *p_x2;
    static __half *pa_xcat, *pa_xn, *pa_ao, *pa_xn2, *pa_gml, *pa_xn3;
    static __half *pw_fc, *pw_qkv, *pw_o, *pw_gu, *pw_down, *pw_lm;
    static __nv_bfloat16 *ph_q, *ph_k, *ph_vt, *ph_p;
    static cudaStream_t s2;
    static cudaEvent_t evFork, evJoin;
    if (!inited) {
        cudaGetSymbolAddress((void**)&p_x0, g_x0);      cudaGetSymbolAddress((void**)&p_qkv, g_qkv);
        cudaGetSymbolAddress((void**)&p_scores, g_scores);
        cudaGetSymbolAddress((void**)&p_x1, g_x1);      cudaGetSymbolAddress((void**)&p_x2, g_x2);
        cudaGetSymbolAddress((void**)&pa_xcat, a_xcat); cudaGetSymbolAddress((void**)&pa_xn, a_xn);
        cudaGetSymbolAddress((void**)&pa_ao, a_ao);     cudaGetSymbolAddress((void**)&pa_xn2, a_xn2);
        cudaGetSymbolAddress((void**)&pa_gml, a_gml);   cudaGetSymbolAddress((void**)&pa_xn3, a_xn3);
        cudaGetSymbolAddress((void**)&pw_fc, w_fc);     cudaGetSymbolAddress((void**)&pw_qkv, w_qkv);
        cudaGetSymbolAddress((void**)&pw_o, w_o);       cudaGetSymbolAddress((void**)&pw_gu, w_gu);
        cudaGetSymbolAddress((void**)&pw_down, w_down); cudaGetSymbolAddress((void**)&pw_lm, w_lm);
        cudaGetSymbolAddress((void**)&ph_q, h_q);       cudaGetSymbolAddress((void**)&ph_k, h_k);
        cudaGetSymbolAddress((void**)&ph_vt, h_vt);     cudaGetSymbolAddress((void**)&ph_p, h_p);
        cudaFuncSetAttribute(gemm_fp16_kernel, cudaFuncAttributeMaxDynamicSharedMemorySize, FGEMM_SMEM);
        cudaFuncSetAttribute(gemm_bf16_kernel, cudaFuncAttributeMaxDynamicSharedMemorySize, BGEMM_SMEM);
        cudaStreamCreateWithFlags(&s2, cudaStreamNonBlocking);
        cudaEventCreateWithFlags(&evFork, cudaEventDisableTiming);
        cudaEventCreateWithFlags(&evJoin, cudaEventDisableTiming);
        inited = true;
    }

    long n4;
    n4 = (long)HH * 2048 / 4;  convert_fp16_kernel<<<(n4 + 255) / 256, 256>>>(fc_w, pw_fc, n4);
    n4 = (long)4096 * HH / 4;  convert_fp16_kernel<<<(n4 + 255) / 256, 256>>>(q_w, pw_qkv, n4);
    n4 = (long)512 * HH / 4;   convert_fp16_kernel<<<(n4 + 255) / 256, 256>>>(k_w, pw_qkv + (size_t)4096 * HH, n4);
    n4 = (long)512 * HH / 4;   convert_fp16_kernel<<<(n4 + 255) / 256, 256>>>(v_w, pw_qkv + (size_t)4608 * HH, n4);

    cudaEventRecord(evFork, 0);
    cudaStreamWaitEvent(s2, evFork, 0);
    n4 = (long)HH * 2048 / 4;  convert_fp16_kernel<<<(n4 + 255) / 256, 256, 0, s2>>>(o_w, pw_o, n4);
    n4 = (long)II * HH / 4;    convert_ileave_kernel<<<(n4 + 255) / 256, 256, 0, s2>>>(gate_w, pw_gu, n4, 0);
    n4 = (long)II * HH / 4;    convert_ileave_kernel<<<(n4 + 255) / 256, 256, 0, s2>>>(up_w,   pw_gu, n4, 1);
    n4 = (long)HH * II / 4;    convert_fp16_kernel<<<(n4 + 255) / 256, 256, 0, s2>>>(down_w, pw_down, n4);
    n4 = (long)VV * HH / 4;    convert_fp16_kernel<<<(n4 + 255) / 256, 256, 0, s2>>>(lm_w, pw_lm, n4);
    cudaEventRecord(evJoin, s2);

    rmsnorm_h_kernel<<<NTOK, 256>>>(embeddings, pre_emb_w, pa_xcat, 2048, 0);
    rmsnorm_h_kernel<<<NTOK, 256>>>(hidden,     pre_hid_w, pa_xcat, 2048, 1024);
    launch_fp16_s(0, pa_xcat, pw_fc, p_x0, nullptr, nullptr, NTOK, HH, 2048, 0);
    rmsnorm_h_kernel<<<NTOK, 256>>>(p_x0, in_ln_w, pa_xn, 1024, 0);
    launch_fp16_s(0, pa_xn, pw_qkv, p_qkv, nullptr, nullptr, NTOK, NQKV, HH, 0);
    qpost_kernel<<<dim3(NTOK, NQH), 256>>>(p_qkv, qn_w, ph_q);
    kpost_kernel<<<dim3(NTOK, NKVH), 256>>>(p_qkv, kn_w, ph_k);
    vpost_kernel<<<dim3(LL / 32, DD / 32, BBATCH * NKVH), 256>>>(p_qkv, ph_vt);
    // scores = QK^T/16 causal (R14 config: CTA 128x128)
    {
        dim3 grid(LL / 128, LL / 128, BBATCH * NQH);
        gemm_bf16_kernel<<<grid, 256, BGEMM_SMEM>>>(ph_q, ph_k, p_scores, nullptr, nullptr,
            LL, LL, DD, (long long)LL * DD, (long long)LL * DD, (long long)LL * LL,
            1, 2, 0.0625f, 0);
    }
    softmax_kernel<<<dim3(LL, BBATCH * NQH), 256>>>(p_scores, ph_p);
    // PV + fused sigmoid gate -> fp16 ao
    {
        dim3 grid(DD / 128, LL / 128, BBATCH * NQH);
        gemm_bf16_kernel<<<grid, 256, BGEMM_SMEM>>>(ph_p, ph_vt, nullptr, p_qkv, pa_ao,
            LL, DD, LL, (long long)LL * LL, (long long)DD * LL, 0,
            1, 3, 1.f, 1);
    }
    cudaStreamWaitEvent(0, evJoin, 0);
    launch_fp16_s(0, pa_ao, pw_o, p_x1, p_x0, nullptr, NTOK, HH, 2048, 1);
    rmsnorm_h_kernel<<<NTOK, 256>>>(p_x1, post_ln_w, pa_xn2, 1024, 0);
    launch_fp16_s(0, pa_xn2, pw_gu, nullptr, nullptr, pa_gml, NTOK, NGU, HH, 4);
    launch_fp16_s(0, pa_gml, pw_down, p_x2, p_x1, nullptr, NTOK, HH, II, 1);
    rmsnorm_h_kernel<<<NTOK, 256>>>(p_x2, norm_w, pa_xn3, 1024, 0);
    launch_fp16_s(0, pa_xn3, pw_lm, out, nullptr, nullptr, NTOK, VV, HH, 0);
}